// round 1
// baseline (speedup 1.0000x reference)
#include <cuda_runtime.h>

#define NQ     10
#define NL     4
#define QDIM   1024
#define BLOCK  256

// Fused per-(layer,qubit) 2x2 complex gate matrices: [NL*NQ][4] = M00,M01,M10,M11
__device__ float2 gM[NL * NQ * 4];

__device__ __forceinline__ float2 cmul(float2 a, float2 b) {
    return make_float2(a.x * b.x - a.y * b.y, a.x * b.y + a.y * b.x);
}
__device__ __forceinline__ float2 cadd(float2 a, float2 b) {
    return make_float2(a.x + b.x, a.y + b.y);
}

// M = Gx(t0) @ Gy(t1) @ Gz(t2)   (state update is psi <- psi @ M)
__global__ void tq_setup_kernel(const float* __restrict__ theta) {
    int t = threadIdx.x;
    if (t >= NL * NQ) return;
    float t0 = theta[t * 3 + 0], t1 = theta[t * 3 + 1], t2 = theta[t * 3 + 2];
    float cx = cosf(0.5f * t0), sx = sinf(0.5f * t0);
    float cy = cosf(0.5f * t1), sy = sinf(0.5f * t1);
    float cz = cosf(0.5f * t2), sz = sinf(0.5f * t2);

    float2 x00 = make_float2(cx, 0.f),  x01 = make_float2(0.f, -sx);
    float2 x10 = make_float2(0.f, -sx), x11 = make_float2(cx, 0.f);
    float2 y00 = make_float2(cy, 0.f),  y01 = make_float2(-sy, 0.f);
    float2 y10 = make_float2(sy, 0.f),  y11 = make_float2(cy, 0.f);

    float2 A00 = cadd(cmul(x00, y00), cmul(x01, y10));
    float2 A01 = cadd(cmul(x00, y01), cmul(x01, y11));
    float2 A10 = cadd(cmul(x10, y00), cmul(x11, y10));
    float2 A11 = cadd(cmul(x10, y01), cmul(x11, y11));

    float2 e0 = make_float2(cz, -sz);   // exp(-i t2/2)
    float2 e1 = make_float2(cz,  sz);   // exp(+i t2/2)

    gM[t * 4 + 0] = cmul(A00, e0);
    gM[t * 4 + 1] = cmul(A01, e1);
    gM[t * 4 + 2] = cmul(A10, e0);
    gM[t * 4 + 3] = cmul(A11, e1);
}

// Composed source index for the CNOT ring (CNOT(q,(q+1)%10) applied q=0..9).
// result[j] = state[cnot_src(j)]
__device__ __forceinline__ int cnot_src(int j) {
    int s = j;
#pragma unroll
    for (int q = 9; q >= 0; --q) {
        int pc = 9 - q;
        int pt = 9 - ((q + 1) % 10);
        s ^= ((s >> pc) & 1) << pt;
    }
    return s;
}

__global__ __launch_bounds__(BLOCK)
void tq_main_kernel(const float* __restrict__ x,
                    const float* __restrict__ W,
                    const float* __restrict__ bias,
                    float* __restrict__ out) {
    __shared__ float2 st[QDIM];
    __shared__ float2 sM[NL * NQ * 4];
    __shared__ float  sc[NQ], ss[NQ];
    __shared__ float  sred[8 * NQ];

    const int b   = blockIdx.x;
    const int tid = threadIdx.x;

    // --- encoding angles: enc_q = pi * tanh(x[b]·W[q] + bias[q]) ---
    if (tid < NQ) {
        float x0 = x[b * 3 + 0], x1 = x[b * 3 + 1], x2 = x[b * 3 + 2];
        float z = x0 * W[tid * 3 + 0] + x1 * W[tid * 3 + 1] + x2 * W[tid * 3 + 2] + bias[tid];
        float e = 3.14159265358979323846f * tanhf(z);
        sc[tid] = cosf(0.5f * e);
        ss[tid] = sinf(0.5f * e);
    }
    for (int i = tid; i < NL * NQ * 4; i += BLOCK) sM[i] = gM[i];
    __syncthreads();

    // --- product-state init (replaces 10 encoding RY gate passes) ---
    // amp[i] = prod_q (bit_q(i) ? -sin : cos); bit_q(i) = (i >> (9-q)) & 1
#pragma unroll
    for (int k = 0; k < 4; ++k) {
        int i = tid + k * BLOCK;
        float v = 1.f;
#pragma unroll
        for (int q = 0; q < NQ; ++q) {
            v *= ((i >> (9 - q)) & 1) ? -ss[q] : sc[q];
        }
        st[i] = make_float2(v, 0.f);
    }
    __syncthreads();

    // --- variational layers: 10 fused gates each; CNOT ring folded into
    //     the next layer's first gate reads (and the final readout) ---
    for (int l = 0; l < NL; ++l) {
#pragma unroll
        for (int q = 0; q < NQ; ++q) {
            const int p = 9 - q;
            const bool fuse = (q == 0) && (l > 0);
            const int base = (l * NQ + q) * 4;
            const float2 M00 = sM[base + 0];
            const float2 M01 = sM[base + 1];
            const float2 M10 = sM[base + 2];
            const float2 M11 = sM[base + 3];

            int   i0[2], i1[2];
            float2 a0[2], a1[2];
#pragma unroll
            for (int r = 0; r < 2; ++r) {
                int pr  = tid + r * BLOCK;
                int low = pr & ((1 << p) - 1);
                i0[r] = ((pr >> p) << (p + 1)) | low;
                i1[r] = i0[r] | (1 << p);
                int r0 = i0[r], r1 = i1[r];
                if (fuse) { r0 = cnot_src(r0); r1 = cnot_src(r1); }
                a0[r] = st[r0];
                a1[r] = st[r1];
            }
            if (fuse) __syncthreads();  // all permuted reads before any write
#pragma unroll
            for (int r = 0; r < 2; ++r) {
                float2 n0, n1;
                n0.x = a0[r].x * M00.x - a0[r].y * M00.y + a1[r].x * M10.x - a1[r].y * M10.y;
                n0.y = a0[r].x * M00.y + a0[r].y * M00.x + a1[r].x * M10.y + a1[r].y * M10.x;
                n1.x = a0[r].x * M01.x - a0[r].y * M01.y + a1[r].x * M11.x - a1[r].y * M11.y;
                n1.y = a0[r].x * M01.y + a0[r].y * M01.x + a1[r].x * M11.y + a1[r].y * M11.x;
                st[i0[r]] = n0;
                st[i1[r]] = n1;
            }
            __syncthreads();
        }
    }

    // --- readout: final CNOT ring folded into the probability gather ---
    float acc[NQ];
#pragma unroll
    for (int q = 0; q < NQ; ++q) acc[q] = 0.f;
#pragma unroll
    for (int k = 0; k < 4; ++k) {
        int j  = tid + k * BLOCK;
        int sj = cnot_src(j);
        float2 a = st[sj];
        float pr = a.x * a.x + a.y * a.y;
#pragma unroll
        for (int q = 0; q < NQ; ++q) {
            acc[q] += ((j >> (9 - q)) & 1) ? -pr : pr;
        }
    }
#pragma unroll
    for (int q = 0; q < NQ; ++q) {
#pragma unroll
        for (int off = 16; off; off >>= 1)
            acc[q] += __shfl_down_sync(0xffffffffu, acc[q], off);
    }
    int warp = tid >> 5, lane = tid & 31;
    if (lane == 0) {
#pragma unroll
        for (int q = 0; q < NQ; ++q) sred[warp * NQ + q] = acc[q];
    }
    __syncthreads();
    if (tid < NQ) {
        float s = 0.f;
#pragma unroll
        for (int w = 0; w < 8; ++w) s += sred[w * NQ + tid];
        out[b * NQ + tid] = s;
    }
}

extern "C" void kernel_launch(void* const* d_in, const int* in_sizes, int n_in,
                              void* d_out, int out_size) {
    const float* x     = (const float*)d_in[0];   // [16384, 3]
    const float* enc_W = (const float*)d_in[1];   // [10, 3]
    const float* enc_b = (const float*)d_in[2];   // [10]
    const float* theta = (const float*)d_in[3];   // [4, 10, 3]
    float* out = (float*)d_out;                   // [16384, 10]

    int batch = in_sizes[0] / 3;

    tq_setup_kernel<<<1, 64>>>(theta);
    tq_main_kernel<<<batch, BLOCK>>>(x, enc_W, enc_b, out);
}

// round 2
// speedup vs baseline: 2.0208x; 2.0208x over previous
#include <cuda_runtime.h>

#define NQ     10
#define NL     4
#define QDIM   1024
#define WPB    4              // warps per block
#define BLOCK  (32 * WPB)

typedef unsigned long long u64;

// Packed gate coefficients: per gate 8 u64 values:
// {P00,Q00,P10,Q10,P01,Q01,P11,Q11} where P(M)=(re,im), Q(M)=(-im,re)
__device__   u64 gPackedBuf[NL * NQ * 8];
__constant__ u64 cG[NL * NQ * 8];

// ---------- packed f32x2 helpers ----------
__device__ __forceinline__ u64 pk2(float a, float b) {
    u64 r; asm("mov.b64 %0, {%1, %2};" : "=l"(r) : "f"(a), "f"(b)); return r;
}
__device__ __forceinline__ void upk(u64 v, float& a, float& b) {
    asm("mov.b64 {%0, %1}, %2;" : "=f"(a), "=f"(b) : "l"(v));
}
__device__ __forceinline__ u64 fma2(u64 a, u64 b, u64 c) {
    u64 d; asm("fma.rn.f32x2 %0, %1, %2, %3;" : "=l"(d) : "l"(a), "l"(b), "l"(c)); return d;
}
__device__ __forceinline__ u64 mul2(u64 a, u64 b) {
    u64 d; asm("mul.rn.f32x2 %0, %1, %2;" : "=l"(d) : "l"(a), "l"(b)); return d;
}

// ---------- setup: fuse Rx*Ry*Rz per (layer,qubit), store packed ----------
struct c2 { float x, y; };
__device__ __forceinline__ c2 cmulh(c2 a, c2 b) { return { a.x*b.x - a.y*b.y, a.x*b.y + a.y*b.x }; }
__device__ __forceinline__ c2 caddh(c2 a, c2 b) { return { a.x + b.x, a.y + b.y }; }

__global__ void tq_setup_kernel(const float* __restrict__ theta) {
    int t = threadIdx.x;
    if (t >= NL * NQ) return;
    float t0 = theta[t*3+0], t1 = theta[t*3+1], t2 = theta[t*3+2];
    float cx = cosf(0.5f*t0), sx = sinf(0.5f*t0);
    float cy = cosf(0.5f*t1), sy = sinf(0.5f*t1);
    float cz = cosf(0.5f*t2), sz = sinf(0.5f*t2);

    c2 x00{cx,0.f}, x01{0.f,-sx}, x10{0.f,-sx}, x11{cx,0.f};
    c2 y00{cy,0.f}, y01{-sy,0.f}, y10{sy,0.f},  y11{cy,0.f};

    c2 A00 = caddh(cmulh(x00,y00), cmulh(x01,y10));
    c2 A01 = caddh(cmulh(x00,y01), cmulh(x01,y11));
    c2 A10 = caddh(cmulh(x10,y00), cmulh(x11,y10));
    c2 A11 = caddh(cmulh(x10,y01), cmulh(x11,y11));

    c2 e0{cz,-sz}, e1{cz,sz};
    c2 M00 = cmulh(A00,e0), M01 = cmulh(A01,e1);
    c2 M10 = cmulh(A10,e0), M11 = cmulh(A11,e1);

    u64* o = &gPackedBuf[t*8];
    o[0] = pk2(M00.x, M00.y);  o[1] = pk2(-M00.y, M00.x);
    o[2] = pk2(M10.x, M10.y);  o[3] = pk2(-M10.y, M10.x);
    o[4] = pk2(M01.x, M01.y);  o[5] = pk2(-M01.y, M01.x);
    o[6] = pk2(M11.x, M11.y);  o[7] = pk2(-M11.y, M11.x);
}

// ---------- gate primitives ----------
// pair update: n0 = a0*M00 + a1*M10 ; n1 = a0*M01 + a1*M11 (complex, packed f32x2)
__device__ __forceinline__ void gpair(float2& A0, float2& A1,
                                      u64 c0, u64 c1, u64 c2_, u64 c3,
                                      u64 c4, u64 c5, u64 c6, u64 c7) {
    u64 r0 = pk2(A0.x, A0.x), i0 = pk2(A0.y, A0.y);
    u64 r1 = pk2(A1.x, A1.x), i1 = pk2(A1.y, A1.y);
    u64 n0 = fma2(i1, c3, fma2(r1, c2_, fma2(i0, c1, mul2(r0, c0))));
    u64 n1 = fma2(i1, c7, fma2(r1, c6,  fma2(i0, c5, mul2(r0, c4))));
    upk(n0, A0.x, A0.y);
    upk(n1, A1.x, A1.y);
}

template<int RB>
__device__ __forceinline__ void gate_reg(float2* st, const u64* c) {
    u64 c0=c[0], c1=c[1], c2_=c[2], c3=c[3], c4=c[4], c5=c[5], c6=c[6], c7=c[7];
#pragma unroll
    for (int k = 0; k < 32; ++k)
        if (!((k >> RB) & 1))
            gpair(st[k], st[k | (1 << RB)], c0, c1, c2_, c3, c4, c5, c6, c7);
}

template<int LB>
__device__ __forceinline__ void gate_lane(float2* st, int lane, const u64* c) {
    int hb = (lane >> LB) & 1;
    u64 Pme = hb ? c[6] : c[0];
    u64 Qme = hb ? c[7] : c[1];
    u64 Pp  = hb ? c[4] : c[2];
    u64 Qp  = hb ? c[5] : c[3];
#pragma unroll
    for (int k = 0; k < 32; ++k) {
        float px = __shfl_xor_sync(0xffffffffu, st[k].x, 1 << LB);
        float py = __shfl_xor_sync(0xffffffffu, st[k].y, 1 << LB);
        u64 mr = pk2(st[k].x, st[k].x), mi = pk2(st[k].y, st[k].y);
        u64 qr = pk2(px, px),           qi = pk2(py, py);
        u64 n = fma2(qi, Qp, fma2(qr, Pp, fma2(mi, Qme, mul2(mr, Pme))));
        upk(n, st[k].x, st[k].y);
    }
}

// ---------- CNOT primitives (bit positions: 0-4 lane, 5-9 = reg bits 0-4) ----------
// reg-ctrl, reg-target: pure static register permutation (free)
template<int RC, int RT>
__device__ __forceinline__ void cnot_rr(float2* st) {
#pragma unroll
    for (int k = 0; k < 32; ++k)
        if (((k >> RC) & 1) && !((k >> RT) & 1)) {
            float2 t = st[k]; st[k] = st[k | (1 << RT)]; st[k | (1 << RT)] = t;
        }
}

// CNOT(pos5 -> pos4): ctrl = reg bit 0, target = lane bit 4
__device__ __forceinline__ void cnot_r0_l4(float2* st) {
#pragma unroll
    for (int k = 1; k < 32; k += 2) {
        st[k].x = __shfl_xor_sync(0xffffffffu, st[k].x, 16);
        st[k].y = __shfl_xor_sync(0xffffffffu, st[k].y, 16);
    }
}

// lane-ctrl, lane-target
template<int LC, int LT>
__device__ __forceinline__ void cnot_ll(float2* st, int lane) {
    bool pr = (lane >> LC) & 1;
#pragma unroll
    for (int k = 0; k < 32; ++k) {
        float vx = __shfl_xor_sync(0xffffffffu, st[k].x, 1 << LT);
        float vy = __shfl_xor_sync(0xffffffffu, st[k].y, 1 << LT);
        st[k].x = pr ? vx : st[k].x;
        st[k].y = pr ? vy : st[k].y;
    }
}

// CNOT(pos0 -> pos9): ctrl = lane bit 0, target = reg bit 4
__device__ __forceinline__ void cnot_l0_r4(float2* st, int lane) {
    bool pr = lane & 1;
#pragma unroll
    for (int k = 0; k < 16; ++k) {
        float2 a = st[k], b = st[k | 16];
        st[k].x      = pr ? b.x : a.x;  st[k].y      = pr ? b.y : a.y;
        st[k | 16].x = pr ? a.x : b.x;  st[k | 16].y = pr ? a.y : b.y;
    }
}

__device__ __forceinline__ void ring(float2* st, int lane) {
    // CNOT(q, q+1) for q=0..9 in order; (ctrl_pos, tgt_pos):
    cnot_rr<4,3>(st);          // (9,8)
    cnot_rr<3,2>(st);          // (8,7)
    cnot_rr<2,1>(st);          // (7,6)
    cnot_rr<1,0>(st);          // (6,5)
    cnot_r0_l4(st);            // (5,4)
    cnot_ll<4,3>(st, lane);    // (4,3)
    cnot_ll<3,2>(st, lane);    // (3,2)
    cnot_ll<2,1>(st, lane);    // (2,1)
    cnot_ll<1,0>(st, lane);    // (1,0)
    cnot_l0_r4(st, lane);      // (0,9)
}

// ---------- main kernel: one warp per batch element, state in registers ----------
__global__ __launch_bounds__(BLOCK)
void tq_main_kernel(const float* __restrict__ x,
                    const float* __restrict__ W,
                    const float* __restrict__ bias,
                    float* __restrict__ out) {
    const int lane = threadIdx.x & 31;
    const int b    = blockIdx.x * WPB + (threadIdx.x >> 5);

    // encoding angles (computed redundantly per lane — tiny)
    float cq[NQ], sq[NQ];
    {
        float x0 = x[b*3+0], x1 = x[b*3+1], x2 = x[b*3+2];
#pragma unroll
        for (int q = 0; q < NQ; ++q) {
            float z = fmaf(x0, W[q*3+0], fmaf(x1, W[q*3+1], fmaf(x2, W[q*3+2], bias[q])));
            float e = 3.14159265358979323846f * tanhf(z);
            sincosf(0.5f * e, &sq[q], &cq[q]);
        }
    }

    // product-state init: amp[(k<<5)|lane] = prod_q (bit ? -s : c)
    float2 st[32];
    {
        float fl = 1.f;
#pragma unroll
        for (int p = 0; p < 5; ++p)                 // lane bits -> qubits 9-p
            fl *= ((lane >> p) & 1) ? -sq[9 - p] : cq[9 - p];
        st[0].x = fl;
#pragma unroll
        for (int bit = 0; bit < 5; ++bit) {          // reg bit -> qubit 4-bit
            int q = 4 - bit;
#pragma unroll
            for (int k = (1 << bit) - 1; k >= 0; --k) {
                st[k | (1 << bit)].x = st[k].x * (-sq[q]);
                st[k].x              = st[k].x * cq[q];
            }
        }
#pragma unroll
        for (int k = 0; k < 32; ++k) st[k].y = 0.f;
    }

    // variational layers
#pragma unroll 1
    for (int l = 0; l < NL; ++l) {
        const u64* cg = &cG[l * NQ * 8];
        gate_reg<4>(st, cg + 0);          // q=0 (pos 9)
        gate_reg<3>(st, cg + 8);          // q=1
        gate_reg<2>(st, cg + 16);         // q=2
        gate_reg<1>(st, cg + 24);         // q=3
        gate_reg<0>(st, cg + 32);         // q=4
        gate_lane<4>(st, lane, cg + 40);  // q=5 (pos 4)
        gate_lane<3>(st, lane, cg + 48);  // q=6
        gate_lane<2>(st, lane, cg + 56);  // q=7
        gate_lane<1>(st, lane, cg + 64);  // q=8
        gate_lane<0>(st, lane, cg + 72);  // q=9
        ring(st, lane);
    }

    // readout: Z expectations
    float tot = 0.f, S[5] = {0.f, 0.f, 0.f, 0.f, 0.f};
#pragma unroll
    for (int k = 0; k < 32; ++k) {
        float p = fmaf(st[k].x, st[k].x, st[k].y * st[k].y);
        tot += p;
#pragma unroll
        for (int bit = 0; bit < 5; ++bit)
            if ((k >> bit) & 1) S[bit] += p;
    }
    float e[NQ];
#pragma unroll
    for (int q = 0; q < 5; ++q)           // reg qubits: bit (4-q) of k
        e[q] = tot - 2.f * S[4 - q];
#pragma unroll
    for (int q = 5; q < NQ; ++q)          // lane qubits: lane bit (9-q)
        e[q] = ((lane >> (9 - q)) & 1) ? -tot : tot;

#pragma unroll
    for (int q = 0; q < NQ; ++q)
#pragma unroll
        for (int off = 16; off; off >>= 1)
            e[q] += __shfl_xor_sync(0xffffffffu, e[q], off);

    if (lane == 0) {
#pragma unroll
        for (int q = 0; q < NQ; ++q) out[b * NQ + q] = e[q];
    }
}

extern "C" void kernel_launch(void* const* d_in, const int* in_sizes, int n_in,
                              void* d_out, int out_size) {
    const float* x     = (const float*)d_in[0];   // [16384, 3]
    const float* enc_W = (const float*)d_in[1];   // [10, 3]
    const float* enc_b = (const float*)d_in[2];   // [10]
    const float* theta = (const float*)d_in[3];   // [4, 10, 3]
    float* out = (float*)d_out;                   // [16384, 10]

    int batch = in_sizes[0] / 3;

    tq_setup_kernel<<<1, 64>>>(theta);

    void* src = nullptr;
    cudaGetSymbolAddress(&src, gPackedBuf);
    cudaMemcpyToSymbolAsync(cG, src, sizeof(u64) * NL * NQ * 8, 0,
                            cudaMemcpyDeviceToDevice, 0);

    tq_main_kernel<<<batch / WPB, BLOCK>>>(x, enc_W, enc_b, out);
}

// round 3
// speedup vs baseline: 2.0231x; 1.0012x over previous
#include <cuda_runtime.h>

#define NQ     10
#define NL     4
#define QDIM   1024
#define WPB    4              // warps per block
#define BLOCK  (32 * WPB)

typedef unsigned long long u64;

// Packed gate coefficients: per gate 8 u64 values:
// {P00,Q00,P10,Q10,P01,Q01,P11,Q11} where P(M)=(re,im), Q(M)=(-im,re)
__device__   u64 gPackedBuf[NL * NQ * 8];
__constant__ u64 cG[NL * NQ * 8];

// ---------- packed f32x2 helpers ----------
__device__ __forceinline__ u64 pk2(float a, float b) {
    u64 r; asm("mov.b64 %0, {%1, %2};" : "=l"(r) : "f"(a), "f"(b)); return r;
}
__device__ __forceinline__ void upk(u64 v, float& a, float& b) {
    asm("mov.b64 {%0, %1}, %2;" : "=f"(a), "=f"(b) : "l"(v));
}
__device__ __forceinline__ u64 fma2(u64 a, u64 b, u64 c) {
    u64 d; asm("fma.rn.f32x2 %0, %1, %2, %3;" : "=l"(d) : "l"(a), "l"(b), "l"(c)); return d;
}
__device__ __forceinline__ u64 mul2(u64 a, u64 b) {
    u64 d; asm("mul.rn.f32x2 %0, %1, %2;" : "=l"(d) : "l"(a), "l"(b)); return d;
}

// ---------- setup: fuse Rx*Ry*Rz per (layer,qubit), store packed ----------
struct c2 { float x, y; };
__device__ __forceinline__ c2 cmulh(c2 a, c2 b) { return { a.x*b.x - a.y*b.y, a.x*b.y + a.y*b.x }; }
__device__ __forceinline__ c2 caddh(c2 a, c2 b) { return { a.x + b.x, a.y + b.y }; }

__global__ void tq_setup_kernel(const float* __restrict__ theta) {
    int t = threadIdx.x;
    if (t >= NL * NQ) return;
    float t0 = theta[t*3+0], t1 = theta[t*3+1], t2 = theta[t*3+2];
    float cx = cosf(0.5f*t0), sx = sinf(0.5f*t0);
    float cy = cosf(0.5f*t1), sy = sinf(0.5f*t1);
    float cz = cosf(0.5f*t2), sz = sinf(0.5f*t2);

    c2 x00{cx,0.f}, x01{0.f,-sx}, x10{0.f,-sx}, x11{cx,0.f};
    c2 y00{cy,0.f}, y01{-sy,0.f}, y10{sy,0.f},  y11{cy,0.f};

    c2 A00 = caddh(cmulh(x00,y00), cmulh(x01,y10));
    c2 A01 = caddh(cmulh(x00,y01), cmulh(x01,y11));
    c2 A10 = caddh(cmulh(x10,y00), cmulh(x11,y10));
    c2 A11 = caddh(cmulh(x10,y01), cmulh(x11,y11));

    c2 e0{cz,-sz}, e1{cz,sz};
    c2 M00 = cmulh(A00,e0), M01 = cmulh(A01,e1);
    c2 M10 = cmulh(A10,e0), M11 = cmulh(A11,e1);

    u64* o = &gPackedBuf[t*8];
    o[0] = pk2(M00.x, M00.y);  o[1] = pk2(-M00.y, M00.x);
    o[2] = pk2(M10.x, M10.y);  o[3] = pk2(-M10.y, M10.x);
    o[4] = pk2(M01.x, M01.y);  o[5] = pk2(-M01.y, M01.x);
    o[6] = pk2(M11.x, M11.y);  o[7] = pk2(-M11.y, M11.x);
}

// ---------- gate primitives ----------
// pair update: n0 = a0*M00 + a1*M10 ; n1 = a0*M01 + a1*M11 (complex, packed f32x2)
__device__ __forceinline__ void gpair(float2& A0, float2& A1,
                                      u64 c0, u64 c1, u64 c2_, u64 c3,
                                      u64 c4, u64 c5, u64 c6, u64 c7) {
    u64 r0 = pk2(A0.x, A0.x), i0 = pk2(A0.y, A0.y);
    u64 r1 = pk2(A1.x, A1.x), i1 = pk2(A1.y, A1.y);
    u64 n0 = fma2(i1, c3, fma2(r1, c2_, fma2(i0, c1, mul2(r0, c0))));
    u64 n1 = fma2(i1, c7, fma2(r1, c6,  fma2(i0, c5, mul2(r0, c4))));
    upk(n0, A0.x, A0.y);
    upk(n1, A1.x, A1.y);
}

template<int RB>
__device__ __forceinline__ void gate_reg(float2* st, const u64* c) {
    u64 c0=c[0], c1=c[1], c2_=c[2], c3=c[3], c4=c[4], c5=c[5], c6=c[6], c7=c[7];
#pragma unroll
    for (int k = 0; k < 32; ++k)
        if (!((k >> RB) & 1))
            gpair(st[k], st[k | (1 << RB)], c0, c1, c2_, c3, c4, c5, c6, c7);
}

template<int LB>
__device__ __forceinline__ void gate_lane(float2* st, int lane, const u64* c) {
    int hb = (lane >> LB) & 1;
    u64 Pme = hb ? c[6] : c[0];
    u64 Qme = hb ? c[7] : c[1];
    u64 Pp  = hb ? c[4] : c[2];
    u64 Qp  = hb ? c[5] : c[3];
#pragma unroll
    for (int k = 0; k < 32; ++k) {
        float px = __shfl_xor_sync(0xffffffffu, st[k].x, 1 << LB);
        float py = __shfl_xor_sync(0xffffffffu, st[k].y, 1 << LB);
        u64 mr = pk2(st[k].x, st[k].x), mi = pk2(st[k].y, st[k].y);
        u64 qr = pk2(px, px),           qi = pk2(py, py);
        u64 n = fma2(qi, Qp, fma2(qr, Pp, fma2(mi, Qme, mul2(mr, Pme))));
        upk(n, st[k].x, st[k].y);
    }
}

// ---------- CNOT primitives (bit positions: 0-4 lane, 5-9 = reg bits 0-4) ----------
// reg-ctrl, reg-target: pure static register permutation (free)
template<int RC, int RT>
__device__ __forceinline__ void cnot_rr(float2* st) {
#pragma unroll
    for (int k = 0; k < 32; ++k)
        if (((k >> RC) & 1) && !((k >> RT) & 1)) {
            float2 t = st[k]; st[k] = st[k | (1 << RT)]; st[k | (1 << RT)] = t;
        }
}

// CNOT(pos5 -> pos4): ctrl = reg bit 0, target = lane bit 4
__device__ __forceinline__ void cnot_r0_l4(float2* st) {
#pragma unroll
    for (int k = 1; k < 32; k += 2) {
        st[k].x = __shfl_xor_sync(0xffffffffu, st[k].x, 16);
        st[k].y = __shfl_xor_sync(0xffffffffu, st[k].y, 16);
    }
}

// lane-ctrl, lane-target
template<int LC, int LT>
__device__ __forceinline__ void cnot_ll(float2* st, int lane) {
    bool pr = (lane >> LC) & 1;
#pragma unroll
    for (int k = 0; k < 32; ++k) {
        float vx = __shfl_xor_sync(0xffffffffu, st[k].x, 1 << LT);
        float vy = __shfl_xor_sync(0xffffffffu, st[k].y, 1 << LT);
        st[k].x = pr ? vx : st[k].x;
        st[k].y = pr ? vy : st[k].y;
    }
}

// CNOT(pos0 -> pos9): ctrl = lane bit 0, target = reg bit 4
__device__ __forceinline__ void cnot_l0_r4(float2* st, int lane) {
    bool pr = lane & 1;
#pragma unroll
    for (int k = 0; k < 16; ++k) {
        float2 a = st[k], b = st[k | 16];
        st[k].x      = pr ? b.x : a.x;  st[k].y      = pr ? b.y : a.y;
        st[k | 16].x = pr ? a.x : b.x;  st[k | 16].y = pr ? a.y : b.y;
    }
}

__device__ __forceinline__ void ring(float2* st, int lane) {
    // CNOT(q, q+1) for q=0..9 in order; (ctrl_pos, tgt_pos):
    cnot_rr<4,3>(st);          // (9,8)
    cnot_rr<3,2>(st);          // (8,7)
    cnot_rr<2,1>(st);          // (7,6)
    cnot_rr<1,0>(st);          // (6,5)
    cnot_r0_l4(st);            // (5,4)
    cnot_ll<4,3>(st, lane);    // (4,3)
    cnot_ll<3,2>(st, lane);    // (3,2)
    cnot_ll<2,1>(st, lane);    // (2,1)
    cnot_ll<1,0>(st, lane);    // (1,0)
    cnot_l0_r4(st, lane);      // (0,9)
}

// ---------- main kernel: one warp per batch element, state in registers ----------
__global__ __launch_bounds__(BLOCK)
void tq_main_kernel(const float* __restrict__ x,
                    const float* __restrict__ W,
                    const float* __restrict__ bias,
                    float* __restrict__ out) {
    const int lane = threadIdx.x & 31;
    const int b    = blockIdx.x * WPB + (threadIdx.x >> 5);

    // encoding angles (computed redundantly per lane — tiny)
    float cq[NQ], sq[NQ];
    {
        float x0 = x[b*3+0], x1 = x[b*3+1], x2 = x[b*3+2];
#pragma unroll
        for (int q = 0; q < NQ; ++q) {
            float z = fmaf(x0, W[q*3+0], fmaf(x1, W[q*3+1], fmaf(x2, W[q*3+2], bias[q])));
            float e = 3.14159265358979323846f * tanhf(z);
            sincosf(0.5f * e, &sq[q], &cq[q]);
        }
    }

    // product-state init: amp[(k<<5)|lane] = prod_q (bit ? -s : c)
    float2 st[32];
    {
        float fl = 1.f;
#pragma unroll
        for (int p = 0; p < 5; ++p)                 // lane bits -> qubits 9-p
            fl *= ((lane >> p) & 1) ? -sq[9 - p] : cq[9 - p];
        st[0].x = fl;
#pragma unroll
        for (int bit = 0; bit < 5; ++bit) {          // reg bit -> qubit 4-bit
            int q = 4 - bit;
#pragma unroll
            for (int k = (1 << bit) - 1; k >= 0; --k) {
                st[k | (1 << bit)].x = st[k].x * (-sq[q]);
                st[k].x              = st[k].x * cq[q];
            }
        }
#pragma unroll
        for (int k = 0; k < 32; ++k) st[k].y = 0.f;
    }

    // variational layers
#pragma unroll 1
    for (int l = 0; l < NL; ++l) {
        const u64* cg = &cG[l * NQ * 8];
        gate_reg<4>(st, cg + 0);          // q=0 (pos 9)
        gate_reg<3>(st, cg + 8);          // q=1
        gate_reg<2>(st, cg + 16);         // q=2
        gate_reg<1>(st, cg + 24);         // q=3
        gate_reg<0>(st, cg + 32);         // q=4
        gate_lane<4>(st, lane, cg + 40);  // q=5 (pos 4)
        gate_lane<3>(st, lane, cg + 48);  // q=6
        gate_lane<2>(st, lane, cg + 56);  // q=7
        gate_lane<1>(st, lane, cg + 64);  // q=8
        gate_lane<0>(st, lane, cg + 72);  // q=9
        ring(st, lane);
    }

    // readout: Z expectations
    float tot = 0.f, S[5] = {0.f, 0.f, 0.f, 0.f, 0.f};
#pragma unroll
    for (int k = 0; k < 32; ++k) {
        float p = fmaf(st[k].x, st[k].x, st[k].y * st[k].y);
        tot += p;
#pragma unroll
        for (int bit = 0; bit < 5; ++bit)
            if ((k >> bit) & 1) S[bit] += p;
    }
    float e[NQ];
#pragma unroll
    for (int q = 0; q < 5; ++q)           // reg qubits: bit (4-q) of k
        e[q] = tot - 2.f * S[4 - q];
#pragma unroll
    for (int q = 5; q < NQ; ++q)          // lane qubits: lane bit (9-q)
        e[q] = ((lane >> (9 - q)) & 1) ? -tot : tot;

#pragma unroll
    for (int q = 0; q < NQ; ++q)
#pragma unroll
        for (int off = 16; off; off >>= 1)
            e[q] += __shfl_xor_sync(0xffffffffu, e[q], off);

    if (lane == 0) {
#pragma unroll
        for (int q = 0; q < NQ; ++q) out[b * NQ + q] = e[q];
    }
}

extern "C" void kernel_launch(void* const* d_in, const int* in_sizes, int n_in,
                              void* d_out, int out_size) {
    const float* x     = (const float*)d_in[0];   // [16384, 3]
    const float* enc_W = (const float*)d_in[1];   // [10, 3]
    const float* enc_b = (const float*)d_in[2];   // [10]
    const float* theta = (const float*)d_in[3];   // [4, 10, 3]
    float* out = (float*)d_out;                   // [16384, 10]

    int batch = in_sizes[0] / 3;

    tq_setup_kernel<<<1, 64>>>(theta);

    void* src = nullptr;
    cudaGetSymbolAddress(&src, gPackedBuf);
    cudaMemcpyToSymbolAsync(cG, src, sizeof(u64) * NL * NQ * 8, 0,
                            cudaMemcpyDeviceToDevice, 0);

    tq_main_kernel<<<batch / WPB, BLOCK>>>(x, enc_W, enc_b, out);
}